// round 1
// baseline (speedup 1.0000x reference)
#include <cuda_runtime.h>
#include <math.h>
#include <math_constants.h>

// Problem constants (fixed by the dataset)
#define BB 64
#define PP 8732
#define OO 50
#define CC 81

// ------------------------- scratch (static device globals) -------------------
__device__ unsigned long long g_key[BB * OO];   // per (b,truth): best prior key
__device__ int   g_conf[BB * PP];               // per (b,prior): target class (0 = background)
__device__ int   g_bti [BB * PP];               // per (b,prior): matched truth idx
__device__ float g_ce  [BB * PP];               // per (b,prior): CE, zeroed at positives
__device__ float g_posce[BB];                   // per batch: sum CE over positives
__device__ int   g_numpos[BB];                  // per batch: #positives
__device__ float g_lossl;
__device__ float g_lossc;
__device__ int   g_npos_tot;

// ------------------------- helpers -------------------------------------------
__device__ __forceinline__ float blockReduceSumF(float v, float* sbuf) {
    int lane = threadIdx.x & 31, w = threadIdx.x >> 5;
    #pragma unroll
    for (int o = 16; o; o >>= 1) v += __shfl_xor_sync(0xFFFFFFFFu, v, o);
    if (lane == 0) sbuf[w] = v;
    __syncthreads();
    int nw = blockDim.x >> 5;
    v = (threadIdx.x < nw) ? sbuf[threadIdx.x] : 0.f;
    if (w == 0) {
        #pragma unroll
        for (int o = 16; o; o >>= 1) v += __shfl_xor_sync(0xFFFFFFFFu, v, o);
    }
    return v;  // valid on thread 0
}

__device__ __forceinline__ int blockReduceSumI(int v, int* sbuf) {
    int lane = threadIdx.x & 31, w = threadIdx.x >> 5;
    #pragma unroll
    for (int o = 16; o; o >>= 1) v += __shfl_xor_sync(0xFFFFFFFFu, v, o);
    if (lane == 0) sbuf[w] = v;
    __syncthreads();
    int nw = blockDim.x >> 5;
    v = (threadIdx.x < nw) ? sbuf[threadIdx.x] : 0;
    if (w == 0) {
        #pragma unroll
        for (int o = 16; o; o >>= 1) v += __shfl_xor_sync(0xFFFFFFFFu, v, o);
    }
    return v;
}

__device__ __forceinline__ float smoothl1(float d) {
    float a = fabsf(d);
    return (a < 1.f) ? 0.5f * d * d : a - 0.5f;
}

// ------------------------- K0: init ------------------------------------------
__global__ void k_init() {
    int t = blockIdx.x * blockDim.x + threadIdx.x;
    if (t < BB * OO) g_key[t] = 0xFFFFFFFFull;  // iou=0, prior index 0
    if (t < BB) { g_posce[t] = 0.f; g_numpos[t] = 0; }
    if (t == 0) { g_lossl = 0.f; g_lossc = 0.f; g_npos_tot = 0; }
}

// ------------------------- K1: matching --------------------------------------
#define CH 1024
__global__ void k_match(const float* __restrict__ targets,
                        const float* __restrict__ priors) {
    int b  = blockIdx.y;
    int p0 = blockIdx.x * CH;
    __shared__ float s_t[OO][4];
    __shared__ float s_area[OO];
    __shared__ float s_lab[OO];
    __shared__ unsigned long long s_key[OO];

    int tid = threadIdx.x;
    for (int i = tid; i < OO; i += blockDim.x) {
        const float* tr = targets + (size_t)(b * OO + i) * 5;
        float x0 = tr[0], y0 = tr[1], x1 = tr[2], y1 = tr[3];
        s_t[i][0] = x0; s_t[i][1] = y0; s_t[i][2] = x1; s_t[i][3] = y1;
        s_area[i] = __fmul_rn(__fsub_rn(x1, x0), __fsub_rn(y1, y0));
        s_lab[i]  = tr[4];
        s_key[i]  = 0xFFFFFFFFull;
    }
    __syncthreads();

    int pend = min(p0 + CH, PP);
    for (int p = p0 + tid; p < pend; p += blockDim.x) {
        float4 pr = ((const float4*)priors)[p];
        float hx = __fmul_rn(pr.z, 0.5f), hy = __fmul_rn(pr.w, 0.5f);
        float bx0 = __fsub_rn(pr.x, hx), by0 = __fsub_rn(pr.y, hy);
        float bx1 = __fadd_rn(pr.x, hx), by1 = __fadd_rn(pr.y, hy);
        float area_b = __fmul_rn(__fsub_rn(bx1, bx0), __fsub_rn(by1, by0));

        float best_inter = -1.f, best_uni = 1.f;
        int   best_o = 0;
        #pragma unroll 5
        for (int o = 0; o < OO; o++) {
            float lx = fmaxf(s_t[o][0], bx0), ly = fmaxf(s_t[o][1], by0);
            float rx = fminf(s_t[o][2], bx1), ry = fminf(s_t[o][3], by1);
            float w = fmaxf(__fsub_rn(rx, lx), 0.f);
            float h = fmaxf(__fsub_rn(ry, ly), 0.f);
            float inter = __fmul_rn(w, h);
            float uni   = __fsub_rn(__fadd_rn(s_area[o], area_b), inter);
            // per-prior argmax over truths (first index wins ties): strict improve
            if (__fmul_rn(inter, best_uni) > __fmul_rn(best_inter, uni)) {
                best_inter = inter; best_uni = uni; best_o = o;
            }
            // per-truth best prior (filter racy, then atomicMax on ordered key)
            unsigned long long cur = s_key[o];
            float curiou = __uint_as_float((unsigned)(cur >> 32));
            if (inter > __fmul_rn(curiou, uni)) {
                float iou = __fdiv_rn(inter, uni);
                unsigned long long nk =
                    ((unsigned long long)__float_as_uint(iou) << 32) |
                    (unsigned long long)(0xFFFFFFFFu - (unsigned)p);
                atomicMax(&s_key[o], nk);
            }
        }
        // threshold: iou < 0.5  <=>  2*inter < union
        int conf = (__fadd_rn(best_inter, best_inter) < best_uni)
                   ? 0 : ((int)s_lab[best_o] + 1);
        g_conf[b * PP + p] = conf;
        g_bti [b * PP + p] = best_o;
    }
    __syncthreads();
    for (int o = tid; o < OO; o += blockDim.x)
        atomicMax(&g_key[b * OO + o], s_key[o]);
}

// --------------- K2: override + smooth-L1 loss + num_pos ---------------------
__global__ void k_override_lossl(const float* __restrict__ targets,
                                 const float* __restrict__ priors,
                                 const float* __restrict__ loc) {
    int b = blockIdx.x, tid = threadIdx.x;
    __shared__ float s_t[OO][5];
    __shared__ float sbufF[32];
    __shared__ int   sbufI[32];

    for (int i = tid; i < OO * 5; i += blockDim.x)
        ((float*)s_t)[i] = targets[(size_t)b * OO * 5 + i];
    __syncthreads();

    if (tid == 0) {
        // sequential last-wins override (mirrors scatter .at[].set semantics)
        for (int o = 0; o < OO; o++) {
            unsigned long long k = g_key[b * OO + o];
            int p = (int)(0xFFFFFFFFu - (unsigned)(k & 0xFFFFFFFFull));
            g_conf[b * PP + p] = (int)s_t[o][4] + 1;
            g_bti [b * PP + p] = o;
        }
    }
    __syncthreads();

    int np = 0; float ll = 0.f;
    for (int p = tid; p < PP; p += blockDim.x) {
        int c = g_conf[b * PP + p];
        if (c > 0) {
            np++;
            int o = g_bti[b * PP + p];
            float4 pr = ((const float4*)priors)[p];
            float m0 = s_t[o][0], m1 = s_t[o][1], m2 = s_t[o][2], m3 = s_t[o][3];
            float cx = __fmul_rn(__fadd_rn(m0, m2), 0.5f);
            float cy = __fmul_rn(__fadd_rn(m1, m3), 0.5f);
            float gx = __fdiv_rn(__fsub_rn(cx, pr.x), __fmul_rn(0.1f, pr.z));
            float gy = __fdiv_rn(__fsub_rn(cy, pr.y), __fmul_rn(0.1f, pr.w));
            float gw = __fdiv_rn(logf(__fdiv_rn(__fsub_rn(m2, m0), pr.z)), 0.2f);
            float gh = __fdiv_rn(logf(__fdiv_rn(__fsub_rn(m3, m1), pr.w)), 0.2f);
            const float* L = loc + (size_t)(b * PP + p) * 4;
            float4 lv = *((const float4*)L);
            ll += smoothl1(lv.x - gx) + smoothl1(lv.y - gy) +
                  smoothl1(lv.z - gw) + smoothl1(lv.w - gh);
        }
    }
    int npT = blockReduceSumI(np, sbufI);
    __syncthreads();
    float llT = blockReduceSumF(ll, sbufF);
    if (tid == 0) {
        g_numpos[b] = npT;
        atomicAdd(&g_npos_tot, npT);
        atomicAdd(&g_lossl, llT);
    }
}

// ------------------------- K3: cross entropy per prior -----------------------
__global__ void k_ce(const float* __restrict__ conf) {
    int gw = blockIdx.x * (blockDim.x >> 5) + (threadIdx.x >> 5);
    if (gw >= BB * PP) return;
    int lane = threadIdx.x & 31;
    const float* row = conf + (size_t)gw * CC;
    float v0 = row[lane];
    float v1 = row[lane + 32];
    float v2 = (lane < CC - 64) ? row[lane + 64] : -CUDART_INF_F;
    float m = fmaxf(fmaxf(v0, v1), v2);
    #pragma unroll
    for (int o = 16; o; o >>= 1) m = fmaxf(m, __shfl_xor_sync(0xFFFFFFFFu, m, o));
    float s = expf(v0 - m) + expf(v1 - m) + ((lane < CC - 64) ? expf(v2 - m) : 0.f);
    #pragma unroll
    for (int o = 16; o; o >>= 1) s += __shfl_xor_sync(0xFFFFFFFFu, s, o);
    if (lane == 0) {
        int tgt = g_conf[gw];
        float ce = logf(s) + m - row[tgt];
        if (tgt > 0) {
            g_ce[gw] = 0.f;
            atomicAdd(&g_posce[gw / PP], ce);
        } else {
            g_ce[gw] = ce;
        }
    }
}

// --------------- K4: per-batch radix top-k + conf loss -----------------------
__global__ void k_topk() {
    int b = blockIdx.x, tid = threadIdx.x;
    __shared__ unsigned int hist[256];
    __shared__ unsigned int sh_prefix;
    __shared__ int sh_rem;
    __shared__ float sbufF[32];

    int np = g_numpos[b];
    int k = min(3 * np, PP - 1);
    const float* ce = g_ce + (size_t)b * PP;

    if (k <= 0) {
        if (tid == 0) atomicAdd(&g_lossc, g_posce[b]);
        return;
    }
    if (tid == 0) { sh_prefix = 0u; sh_rem = k; }

    for (int pass = 0; pass < 4; pass++) {
        int shift = 24 - 8 * pass;
        if (tid < 256) hist[tid] = 0u;
        __syncthreads();
        unsigned pfx = sh_prefix;
        for (int p = tid; p < PP; p += blockDim.x) {
            unsigned key = __float_as_uint(ce[p]);
            bool ok = (pass == 0) || ((key >> (shift + 8)) == (pfx >> (shift + 8)));
            if (ok) atomicAdd(&hist[(key >> shift) & 255u], 1u);
        }
        __syncthreads();
        if (tid == 0) {
            int rem = sh_rem;
            int d = 255;
            for (; d > 0; d--) {
                int c = (int)hist[d];
                if (rem <= c) break;
                rem -= c;
            }
            sh_prefix = pfx | ((unsigned)d << shift);
            sh_rem = rem;
        }
        __syncthreads();
    }
    unsigned T = sh_prefix;
    int rem = sh_rem;
    float tv = __uint_as_float(T);
    float sum = 0.f;
    for (int p = tid; p < PP; p += blockDim.x) {
        float v = ce[p];
        if (__float_as_uint(v) > T) sum += v;
    }
    float sumT = blockReduceSumF(sum, sbufF);
    if (tid == 0)
        atomicAdd(&g_lossc, g_posce[b] + sumT + tv * (float)rem);
}

// ------------------------- K5: finalize --------------------------------------
__global__ void k_final(float* __restrict__ out) {
    float N = (float)g_npos_tot;
    out[0] = g_lossl / N;
    out[1] = g_lossc / N;
}

// ------------------------- launch --------------------------------------------
extern "C" void kernel_launch(void* const* d_in, const int* in_sizes, int n_in,
                              void* d_out, int out_size) {
    const float* loc     = (const float*)d_in[0];
    const float* conf    = (const float*)d_in[1];
    const float* targets = (const float*)d_in[2];
    const float* priors  = (const float*)d_in[3];
    float* out = (float*)d_out;

    k_init<<<(BB * OO + 255) / 256, 256>>>();

    dim3 g1((PP + CH - 1) / CH, BB);
    k_match<<<g1, 256>>>(targets, priors);

    k_override_lossl<<<BB, 512>>>(targets, priors, loc);

    int nwarps = BB * PP;
    int blocks = (nwarps + 7) / 8;
    k_ce<<<blocks, 256>>>(conf);

    k_topk<<<BB, 256>>>();

    k_final<<<1, 1>>>(out);
}

// round 2
// speedup vs baseline: 1.0412x; 1.0412x over previous
#include <cuda_runtime.h>
#include <math.h>
#include <math_constants.h>

// Problem constants (fixed by the dataset)
#define BB 64
#define PP 8732
#define OO 50
#define CC 81

#define CH 1024                        // priors per match block
#define MB ((PP + CH - 1) / CH)        // match chunks per batch = 9
#define NMATCH (BB * MB)               // match blocks = 576
#define LSE_WPB 8                      // warps per lse block
#define NLSE ((BB * PP + LSE_WPB - 1) / LSE_WPB)

// ------------------------- scratch (static device globals) -------------------
__device__ unsigned long long g_key[BB * OO];   // per (b,truth): best prior key
__device__ int   g_conf[BB * PP];               // per (b,prior): target class (0 = bg)
__device__ int   g_bti [BB * PP];               // per (b,prior): matched truth idx
__device__ float g_lse [BB * PP];               // per (b,prior): logsumexp
__device__ float g_lossl;
__device__ float g_lossc;
__device__ int   g_npos_tot;

// ------------------------- helpers -------------------------------------------
__device__ __forceinline__ float blockReduceSumF(float v, float* sbuf) {
    int lane = threadIdx.x & 31, w = threadIdx.x >> 5;
    #pragma unroll
    for (int o = 16; o; o >>= 1) v += __shfl_xor_sync(0xFFFFFFFFu, v, o);
    if (lane == 0) sbuf[w] = v;
    __syncthreads();
    int nw = blockDim.x >> 5;
    v = (threadIdx.x < nw) ? sbuf[threadIdx.x] : 0.f;
    if (w == 0) {
        #pragma unroll
        for (int o = 16; o; o >>= 1) v += __shfl_xor_sync(0xFFFFFFFFu, v, o);
    }
    return v;  // valid on thread 0
}

__device__ __forceinline__ int blockReduceSumI(int v, int* sbuf) {
    int lane = threadIdx.x & 31, w = threadIdx.x >> 5;
    #pragma unroll
    for (int o = 16; o; o >>= 1) v += __shfl_xor_sync(0xFFFFFFFFu, v, o);
    if (lane == 0) sbuf[w] = v;
    __syncthreads();
    int nw = blockDim.x >> 5;
    v = (threadIdx.x < nw) ? sbuf[threadIdx.x] : 0;
    if (w == 0) {
        #pragma unroll
        for (int o = 16; o; o >>= 1) v += __shfl_xor_sync(0xFFFFFFFFu, v, o);
    }
    return v;
}

__device__ __forceinline__ float smoothl1(float d) {
    float a = fabsf(d);
    return (a < 1.f) ? 0.5f * d * d : a - 0.5f;
}

// ------------------------- K0: init ------------------------------------------
__global__ void k_init() {
    int t = blockIdx.x * blockDim.x + threadIdx.x;
    if (t < BB * OO) g_key[t] = 0xFFFFFFFFull;  // iou=0, prior index 0
    if (t == 0) { g_lossl = 0.f; g_lossc = 0.f; g_npos_tot = 0; }
}

// ---------------- K1: fat kernel = matching blocks + logsumexp blocks --------
__global__ void k_fat(const float* __restrict__ targets,
                      const float* __restrict__ priors,
                      const float* __restrict__ conf) {
    if (blockIdx.x < NMATCH) {
        // ================= matching =================
        int mb = blockIdx.x;
        int b  = mb / MB;
        int p0 = (mb % MB) * CH;
        __shared__ float s_t[OO][4];
        __shared__ float s_area[OO];
        __shared__ float s_lab[OO];
        __shared__ unsigned long long s_key[OO];

        int tid = threadIdx.x;
        for (int i = tid; i < OO; i += blockDim.x) {
            const float* tr = targets + (size_t)(b * OO + i) * 5;
            float x0 = tr[0], y0 = tr[1], x1 = tr[2], y1 = tr[3];
            s_t[i][0] = x0; s_t[i][1] = y0; s_t[i][2] = x1; s_t[i][3] = y1;
            s_area[i] = __fmul_rn(__fsub_rn(x1, x0), __fsub_rn(y1, y0));
            s_lab[i]  = tr[4];
            s_key[i]  = 0xFFFFFFFFull;
        }
        __syncthreads();

        int pend = min(p0 + CH, PP);
        for (int p = p0 + tid; p < pend; p += blockDim.x) {
            float4 pr = ((const float4*)priors)[p];
            float hx = __fmul_rn(pr.z, 0.5f), hy = __fmul_rn(pr.w, 0.5f);
            float bx0 = __fsub_rn(pr.x, hx), by0 = __fsub_rn(pr.y, hy);
            float bx1 = __fadd_rn(pr.x, hx), by1 = __fadd_rn(pr.y, hy);
            float area_b = __fmul_rn(__fsub_rn(bx1, bx0), __fsub_rn(by1, by0));

            float best_inter = -1.f, best_uni = 1.f;
            int   best_o = 0;
            #pragma unroll 5
            for (int o = 0; o < OO; o++) {
                float lx = fmaxf(s_t[o][0], bx0), ly = fmaxf(s_t[o][1], by0);
                float rx = fminf(s_t[o][2], bx1), ry = fminf(s_t[o][3], by1);
                float w = fmaxf(__fsub_rn(rx, lx), 0.f);
                float h = fmaxf(__fsub_rn(ry, ly), 0.f);
                float inter = __fmul_rn(w, h);
                float uni   = __fsub_rn(__fadd_rn(s_area[o], area_b), inter);
                // per-prior argmax over truths (first index wins ties)
                if (__fmul_rn(inter, best_uni) > __fmul_rn(best_inter, uni)) {
                    best_inter = inter; best_uni = uni; best_o = o;
                }
                // per-truth best prior (racy filter, then atomicMax on key)
                unsigned long long cur = s_key[o];
                float curiou = __uint_as_float((unsigned)(cur >> 32));
                if (inter > __fmul_rn(curiou, uni)) {
                    float iou = __fdiv_rn(inter, uni);
                    unsigned long long nk =
                        ((unsigned long long)__float_as_uint(iou) << 32) |
                        (unsigned long long)(0xFFFFFFFFu - (unsigned)p);
                    atomicMax(&s_key[o], nk);
                }
            }
            // threshold: iou < 0.5  <=>  2*inter < union
            int conf_t = (__fadd_rn(best_inter, best_inter) < best_uni)
                         ? 0 : ((int)s_lab[best_o] + 1);
            g_conf[b * PP + p] = conf_t;
            g_bti [b * PP + p] = best_o;
        }
        __syncthreads();
        for (int o = tid; o < OO; o += blockDim.x)
            atomicMax(&g_key[b * OO + o], s_key[o]);
    } else {
        // ================= logsumexp per prior =================
        int gw = (blockIdx.x - NMATCH) * LSE_WPB + (threadIdx.x >> 5);
        if (gw >= BB * PP) return;
        int lane = threadIdx.x & 31;
        const float* row = conf + (size_t)gw * CC;
        float v0 = row[lane];
        float v1 = row[lane + 32];
        float v2 = (lane < CC - 64) ? row[lane + 64] : -CUDART_INF_F;
        float m = fmaxf(fmaxf(v0, v1), v2);
        #pragma unroll
        for (int o = 16; o; o >>= 1) m = fmaxf(m, __shfl_xor_sync(0xFFFFFFFFu, m, o));
        float s = __expf(v0 - m) + __expf(v1 - m) +
                  ((lane < CC - 64) ? __expf(v2 - m) : 0.f);
        #pragma unroll
        for (int o = 16; o; o >>= 1) s += __shfl_xor_sync(0xFFFFFFFFu, s, o);
        if (lane == 0) g_lse[gw] = __logf(s) + m;
    }
}

// --------------- K2: override + smooth-L1 loss + num_pos ---------------------
__global__ void k_override_lossl(const float* __restrict__ targets,
                                 const float* __restrict__ priors,
                                 const float* __restrict__ loc) {
    int b = blockIdx.x, tid = threadIdx.x;
    __shared__ float s_t[OO][5];
    __shared__ float sbufF[32];
    __shared__ int   sbufI[32];

    for (int i = tid; i < OO * 5; i += blockDim.x)
        ((float*)s_t)[i] = targets[(size_t)b * OO * 5 + i];
    __syncthreads();

    if (tid == 0) {
        // sequential last-wins override (mirrors scatter .at[].set semantics)
        for (int o = 0; o < OO; o++) {
            unsigned long long k = g_key[b * OO + o];
            int p = (int)(0xFFFFFFFFu - (unsigned)(k & 0xFFFFFFFFull));
            g_conf[b * PP + p] = (int)s_t[o][4] + 1;
            g_bti [b * PP + p] = o;
        }
    }
    __syncthreads();

    int np = 0; float ll = 0.f;
    for (int p = tid; p < PP; p += blockDim.x) {
        int c = g_conf[b * PP + p];
        if (c > 0) {
            np++;
            int o = g_bti[b * PP + p];
            float4 pr = ((const float4*)priors)[p];
            float m0 = s_t[o][0], m1 = s_t[o][1], m2 = s_t[o][2], m3 = s_t[o][3];
            float cx = __fmul_rn(__fadd_rn(m0, m2), 0.5f);
            float cy = __fmul_rn(__fadd_rn(m1, m3), 0.5f);
            float gx = __fdiv_rn(__fsub_rn(cx, pr.x), __fmul_rn(0.1f, pr.z));
            float gy = __fdiv_rn(__fsub_rn(cy, pr.y), __fmul_rn(0.1f, pr.w));
            float gw = __fdiv_rn(logf(__fdiv_rn(__fsub_rn(m2, m0), pr.z)), 0.2f);
            float gh = __fdiv_rn(logf(__fdiv_rn(__fsub_rn(m3, m1), pr.w)), 0.2f);
            const float* L = loc + (size_t)(b * PP + p) * 4;
            float4 lv = *((const float4*)L);
            ll += smoothl1(lv.x - gx) + smoothl1(lv.y - gy) +
                  smoothl1(lv.z - gw) + smoothl1(lv.w - gh);
        }
    }
    int npT = blockReduceSumI(np, sbufI);
    __syncthreads();
    float llT = blockReduceSumF(ll, sbufF);
    if (tid == 0) {
        atomicAdd(&g_npos_tot, npT);
        atomicAdd(&g_lossl, llT);
    }
}

// --------------- K3: per-batch CE finalize + radix top-k + conf loss ---------
__global__ void k_ce_topk(const float* __restrict__ conf) {
    int b = blockIdx.x, tid = threadIdx.x;
    __shared__ float s_ce[PP];                 // 34928 B
    __shared__ unsigned int hist[256];
    __shared__ unsigned int sh_prefix;
    __shared__ int sh_rem;
    __shared__ float sbufF[32];
    __shared__ int   sbufI[32];
    __shared__ float sh_posce;
    __shared__ int   sh_np;

    // ce = lse - row[tgt]; positives contribute to posce and are zeroed for mining
    float posce = 0.f; int np = 0;
    for (int p = tid; p < PP; p += blockDim.x) {
        int idx = b * PP + p;
        int tgt = g_conf[idx];
        float ce = g_lse[idx] - conf[(size_t)idx * CC + tgt];
        if (tgt > 0) { posce += ce; np++; s_ce[p] = 0.f; }
        else s_ce[p] = ce;
    }
    int npT = blockReduceSumI(np, sbufI);
    __syncthreads();
    float pcT = blockReduceSumF(posce, sbufF);
    if (tid == 0) { sh_np = npT; sh_posce = pcT; }
    __syncthreads();

    int k = min(3 * sh_np, PP - 1);
    if (k <= 0) {
        if (tid == 0) atomicAdd(&g_lossc, sh_posce);
        return;
    }
    if (tid == 0) { sh_prefix = 0u; sh_rem = k; }
    __syncthreads();

    // exact radix select of k-th largest (ce >= 0 so uint order == float order)
    for (int pass = 0; pass < 4; pass++) {
        int shift = 24 - 8 * pass;
        if (tid < 256) hist[tid] = 0u;
        __syncthreads();
        unsigned pfx = sh_prefix;
        for (int p = tid; p < PP; p += blockDim.x) {
            unsigned key = __float_as_uint(s_ce[p]);
            bool ok = (pass == 0) || ((key >> (shift + 8)) == (pfx >> (shift + 8)));
            if (ok) atomicAdd(&hist[(key >> shift) & 255u], 1u);
        }
        __syncthreads();
        if (tid == 0) {
            int rem = sh_rem;
            int d = 255;
            for (; d > 0; d--) {
                int c = (int)hist[d];
                if (rem <= c) break;
                rem -= c;
            }
            sh_prefix = pfx | ((unsigned)d << shift);
            sh_rem = rem;
        }
        __syncthreads();
    }
    unsigned T = sh_prefix;
    int rem = sh_rem;
    float tv = __uint_as_float(T);
    float sum = 0.f;
    for (int p = tid; p < PP; p += blockDim.x) {
        float v = s_ce[p];
        if (__float_as_uint(v) > T) sum += v;
    }
    float sumT = blockReduceSumF(sum, sbufF);
    if (tid == 0)
        atomicAdd(&g_lossc, sh_posce + sumT + tv * (float)rem);
}

// ------------------------- K4: finalize --------------------------------------
__global__ void k_final(float* __restrict__ out) {
    float N = (float)g_npos_tot;
    out[0] = g_lossl / N;
    out[1] = g_lossc / N;
}

// ------------------------- launch --------------------------------------------
extern "C" void kernel_launch(void* const* d_in, const int* in_sizes, int n_in,
                              void* d_out, int out_size) {
    const float* loc     = (const float*)d_in[0];
    const float* conf    = (const float*)d_in[1];
    const float* targets = (const float*)d_in[2];
    const float* priors  = (const float*)d_in[3];
    float* out = (float*)d_out;

    k_init<<<(BB * OO + 255) / 256, 256>>>();

    k_fat<<<NMATCH + NLSE, 256>>>(targets, priors, conf);

    k_override_lossl<<<BB, 512>>>(targets, priors, loc);

    k_ce_topk<<<BB, 1024>>>(conf);

    k_final<<<1, 1>>>(out);
}